// round 17
// baseline (speedup 1.0000x reference)
#include <cuda_runtime.h>
#include <cuda_fp16.h>
#include <cstdint>
#include <math.h>

// ---------------- problem constants ----------------
#define HID    2048
#define BROWS  4096
#define KHALF  2048

constexpr int BM = 128;
constexpr int BN = 128;              // C cols per CTA (col = h*4+g -> 32 hidden cols)
constexpr int BK = 32;               // K per tile (2 mma k16 steps)
constexpr int NT = 4096 / BK;        // 128 k-tiles
constexpr int NPAIRS = NT / 2;       // 64
constexpr int NUM_NT = (4 * HID) / BN;  // 64 n-tiles
constexpr int GROUP_M = 8;
constexpr int NTHREADS = 256;        // 8 warps, 2 CTAs/SM

// Pre-converted fp16 tensors in the EXACT smem tile image layout.
__device__ __half g_a[16777216];     // 32 MB: [128 tiles][4096 rows][32 halfs]
__device__ __half g_w[33554432];     // 64 MB: [128 tiles][8192 cols][32 halfs]

// ---------------- smem layout (GEMM) ----------------
constexpr int TILE_BH = 8192;
constexpr int SM_A0 = 1024;                      // A: 6 slots = 48KB
constexpr int SM_B0 = SM_A0 + 6 * TILE_BH;       // B: 6 slots = 48KB
constexpr int CSTRIDE = 132;
constexpr int SM_C = 1024;
constexpr int SMEM_TOTAL = SM_B0 + 6 * TILE_BH;  // 99328

constexpr size_t A_TSTRIDE = 4096 * 64;          // bytes per A k-tile
constexpr size_t B_TSTRIDE = 8192 * 64;          // bytes per B k-tile

__device__ __forceinline__ float sigm(float v) { return 1.f / (1.f + __expf(-v)); }
__device__ __forceinline__ uint32_t h2u(__half2 h) { return *(uint32_t*)&h; }

__device__ __forceinline__ int perm_word(int m, int sw) {
    int w = (m & 3) * 4 + ((m >> 3) & 1) * 2 + ((m >> 2) & 1);
    return (((w >> 2) ^ sw) << 2) + (w & 3);
}

// ---------------- convert kernel (smem-staged, coalesced stores) ----------------
// 49152 blocks x 256 threads. Each block produces one contiguous 2KB chunk
// (32 rows x 64B) of the destination tile image.
//   blocks [0,8192)      : x  -> g_a tiles 0..63    (128 row-blocks per tile)
//   blocks [8192,16384)  : hx -> g_a tiles 64..127
//   blocks [16384,32768) : Wx -> g_w tiles 0..63    (256 col-blocks per tile)
//   blocks [32768,49152) : Wh -> g_w tiles 64..127
__global__ void convert_all(const float* __restrict__ x,  const float* __restrict__ hx,
                            const float* __restrict__ Wx, const float* __restrict__ Wh)
{
    __shared__ uint32_t stage[512];          // 32 rows x 16 words = 2KB
    const int bid  = blockIdx.x;
    const int tid  = threadIdx.x;
    const int kq   = tid & 7;
    const int lrow = tid >> 3;               // 0..31
    const int sw   = (lrow >> 1) & 1;        // granule swizzle bit (row0 % 32 == 0)

    const float* srcAddr;
    char* dst;
    if (bid < 16384) {                       // A path (4096 rows per tile)
        const float* src = (bid < 8192) ? x : hx;
        const int tbase  = (bid < 8192) ? 0 : 64;
        const int sid = bid & 8191;
        const int t   = sid >> 7;
        const int r0  = (sid & 127) * 32;
        srcAddr = src + (size_t)(r0 + lrow) * KHALF + t * BK + kq * 4;
        dst = (char*)g_a + ((size_t)(tbase + t) * 4096 + r0) * 64;
    } else {                                 // W path (8192 interleaved cols per tile)
        const int wb = bid - 16384;
        const float* src = (wb < 16384) ? Wx : Wh;
        const int tbase  = (wb < 16384) ? 0 : 64;
        const int sid = wb & 16383;
        const int t   = sid >> 8;
        const int c0  = (sid & 255) * 32;
        const int c   = c0 + lrow;           // interleaved col = j*4 + gate
        const int j = c >> 2, gate = c & 3;
        srcAddr = src + (size_t)(gate * HID + j) * KHALF + t * BK + kq * 4;
        dst = (char*)g_w + ((size_t)(tbase + t) * 8192 + c0) * 64;
    }

    float4 v = *(const float4*)srcAddr;
    stage[lrow * 16 + perm_word(2 * kq,     sw)] = h2u(__floats2half2_rn(v.x, v.y));
    stage[lrow * 16 + perm_word(2 * kq + 1, sw)] = h2u(__floats2half2_rn(v.z, v.w));
    __syncthreads();
    *(uint2*)(dst + tid * 8) = *(uint2*)&stage[tid * 2];   // fully coalesced
}

// ---------------- GEMM helpers ----------------
__device__ __forceinline__ uint32_t s2u(const void* p) {
    uint32_t a;
    asm("{ .reg .u64 t; cvta.to.shared.u64 t, %1; cvt.u32.u64 %0, t; }" : "=r"(a) : "l"(p));
    return a;
}
__device__ __forceinline__ void cpa16(uint32_t s, const void* g) {
    asm volatile("cp.async.cg.shared.global [%0], [%1], 16;" :: "r"(s), "l"(g));
}
__device__ __forceinline__ void lds128(uint4& v, uint32_t addr) {
    asm volatile("ld.shared.v4.b32 {%0,%1,%2,%3}, [%4];"
                 : "=r"(v.x), "=r"(v.y), "=r"(v.z), "=r"(v.w) : "r"(addr));
}
__device__ __forceinline__ void mma_f16(float& c0, float& c1, float& c2, float& c3,
                                        uint32_t a0, uint32_t a1, uint32_t a2, uint32_t a3,
                                        uint32_t b0, uint32_t b1) {
    asm volatile(
        "mma.sync.aligned.m16n8k16.row.col.f32.f16.f16.f32 "
        "{%0,%1,%2,%3}, {%4,%5,%6,%7}, {%8,%9}, {%0,%1,%2,%3};"
        : "+f"(c0), "+f"(c1), "+f"(c2), "+f"(c3)
        : "r"(a0), "r"(a1), "r"(a2), "r"(a3), "r"(b0), "r"(b1));
}

// ---------------- GEMM + fused LSTM kernel ----------------
__global__ __launch_bounds__(NTHREADS, 2)
void lstm_gemm(const float* __restrict__ cx,
               const float* __restrict__ bx,
               const float* __restrict__ bh,
               float* __restrict__ out)
{
    extern __shared__ __align__(1024) uint8_t smem[];
    const uint32_t sbase = s2u(smem);
    const int tid  = threadIdx.x;
    const int wid  = tid >> 5;
    const int lane = tid & 31;
    const int g    = lane >> 2;
    const int tig  = lane & 3;
    const int wpar = wid & 1;               // warp parity: desync tile order

    // ---- CTA tile mapping ----
    int bid    = blockIdx.x;
    int group  = bid / (GROUP_M * NUM_NT);
    int rem    = bid % (GROUP_M * NUM_NT);
    int m_tile = group * GROUP_M + (rem % GROUP_M);
    int n_tile = rem / GROUP_M;
    const int m0 = m_tile * BM;
    const int j0 = n_tile * (BN / 4);

    // ---- hoisted bases ----
    const int wm = (wid >> 2) * 64;
    const int wn = (wid & 3) * 32;
    const int cgo = (tig ^ ((g >> 1) & 1)) << 4;
    const uint32_t aAddr = sbase + SM_A0 + (uint32_t)((wm + g) * 64 + cgo);
    const uint32_t bAddr = sbase + SM_B0 + (uint32_t)((wn + g) * 64 + cgo);
    const uint32_t csa   = sbase + SM_A0 + (uint32_t)(tid * 16);
    const uint32_t csb   = sbase + SM_B0 + (uint32_t)(tid * 16);
    const char* gA = (const char*)g_a + (size_t)m0 * 64 + tid * 16;
    const char* gB = (const char*)g_w + (size_t)(4 * j0) * 64 + tid * 16;

    auto issue_tile = [&](int sl, const char* ga, const char* gb) {
        cpa16(csa + sl * TILE_BH,        ga);
        cpa16(csa + sl * TILE_BH + 4096, ga + 4096);
        cpa16(csb + sl * TILE_BH,        gb);
        cpa16(csb + sl * TILE_BH + 4096, gb + 4096);
    };
    auto commit = [&]() { asm volatile("cp.async.commit_group;" ::: "memory"); };

    float acc[4][4][4];
#pragma unroll
    for (int mi = 0; mi < 4; mi++)
#pragma unroll
        for (int ni = 0; ni < 4; ni++)
#pragma unroll
            for (int q = 0; q < 4; q++) acc[mi][ni][q] = 0.f;

    auto mma_slot = [&](int sl) {
        uint4 vB[4];
#pragma unroll
        for (int ni = 0; ni < 4; ni++)
            lds128(vB[ni], bAddr + sl * TILE_BH + ni * 512);
#pragma unroll
        for (int mi = 0; mi < 4; mi++) {
            uint4 vA0, vA1;
            lds128(vA0, aAddr + sl * TILE_BH + mi * 1024);
            lds128(vA1, aAddr + sl * TILE_BH + mi * 1024 + 512);
#pragma unroll
            for (int ni = 0; ni < 4; ni++) {
                mma_f16(acc[mi][ni][0], acc[mi][ni][1], acc[mi][ni][2], acc[mi][ni][3],
                        vA0.x, vA1.x, vA0.y, vA1.y, vB[ni].x, vB[ni].y);
                mma_f16(acc[mi][ni][0], acc[mi][ni][1], acc[mi][ni][2], acc[mi][ni][3],
                        vA0.z, vA1.z, vA0.w, vA1.w, vB[ni].z, vB[ni].w);
            }
        }
    };

    // ---- prologue: issue pairs 0 (slots 0/1) and 1 (slots 2/3) ----
    issue_tile(0, gA, gB);
    issue_tile(1, gA + A_TSTRIDE, gB + B_TSTRIDE);
    commit();
    issue_tile(2, gA + 2 * A_TSTRIDE, gB + 2 * B_TSTRIDE);
    issue_tile(3, gA + 3 * A_TSTRIDE, gB + 3 * B_TSTRIDE);
    commit();
    const char* gAn = gA + 4 * A_TSTRIDE;   // next pair to issue: pair 2
    const char* gBn = gB + 4 * B_TSTRIDE;

    // ---- mainloop: one sync per pair; warp-parity tile order ----
#pragma unroll 1
    for (int blk = 0; blk < 21; blk++) {
        const int pbase = 3 * blk;
#pragma unroll
        for (int q = 0; q < 3; q++) {
            const int p   = pbase + q;
            const int s0  = 2 * q;                    // this pair's slots
            const int sis = 2 * ((q + 2) % 3);        // issue target = (p-1)%3 slots
            asm volatile("cp.async.wait_group 1;" ::: "memory");
            __syncthreads();                          // pair p ready; p-1 fully consumed
            if (p + 2 < NPAIRS)
                issue_tile(sis, gAn, gBn);            // tile 0 of pair p+2
            mma_slot(s0 + wpar);                      // even warps: s0; odd: s0+1
            if (p + 2 < NPAIRS) {
                issue_tile(sis + 1, gAn + A_TSTRIDE, gBn + B_TSTRIDE);
                commit();
                gAn += 2 * A_TSTRIDE;
                gBn += 2 * B_TSTRIDE;
            }
            mma_slot(s0 + 1 - wpar);
        }
    }
    // ---- tail: pair 63 (slots 0,1) ----
    asm volatile("cp.async.wait_group 0;" ::: "memory");
    __syncthreads();
    mma_slot(wpar);
    mma_slot(1 - wpar);

    // ---- epilogue: stage C through smem, then fused LSTM math ----
    __syncthreads();
    float* Cs = (float*)(smem + SM_C);
#pragma unroll
    for (int mi = 0; mi < 4; mi++) {
#pragma unroll
        for (int ni = 0; ni < 4; ni++) {
            const int r1 = wm + mi * 16 + g;
            const int c0 = wn + ni * 8 + tig * 2;
            *(float2*)(Cs + r1 * CSTRIDE + c0)       = make_float2(acc[mi][ni][0], acc[mi][ni][1]);
            *(float2*)(Cs + (r1 + 8) * CSTRIDE + c0) = make_float2(acc[mi][ni][2], acc[mi][ni][3]);
        }
    }
    __syncthreads();

    const int j = j0 + lane;
    const float bs0 = bx[0 * HID + j] + bh[0 * HID + j];
    const float bs1 = bx[1 * HID + j] + bh[1 * HID + j];
    const float bs2 = bx[2 * HID + j] + bh[2 * HID + j];
    const float bs3 = bx[3 * HID + j] + bh[3 * HID + j];

#pragma unroll
    for (int i = 0; i < 16; i++) {
        const int rl  = i * 8 + wid;
        const int row = m0 + rl;
        const float4 gv = *(const float4*)(Cs + rl * CSTRIDE + lane * 4);
        const float f_ = sigm (gv.x + bs0);
        const float i_ = sigm (gv.y + bs1);
        const float c_ = tanhf(gv.z + bs2);
        const float o_ = sigm (gv.w + bs3);
        const float cv = cx[(size_t)row * HID + j];
        const float cy = f_ * cv + i_ * c_;
        const float hy = o_ * tanhf(cy);
        out[(size_t)row * HID + j] = hy;
        out[(size_t)BROWS * HID + (size_t)row * HID + j] = cy;
    }
}

extern "C" void kernel_launch(void* const* d_in, const int* in_sizes, int n_in,
                              void* d_out, int out_size)
{
    const float* x  = (const float*)d_in[0];
    const float* hx = (const float*)d_in[1];
    const float* cx = (const float*)d_in[2];
    const float* Wx = (const float*)d_in[3];
    const float* bx = (const float*)d_in[4];
    const float* Wh = (const float*)d_in[5];
    const float* bh = (const float*)d_in[6];
    float* out = (float*)d_out;

    cudaFuncSetAttribute(lstm_gemm,
                         cudaFuncAttributeMaxDynamicSharedMemorySize, SMEM_TOTAL);

    convert_all<<<49152, 256>>>(x, hx, Wx, Wh);

    const int grid = (BROWS / BM) * NUM_NT;       // 2048
    lstm_gemm<<<grid, NTHREADS, SMEM_TOTAL>>>(cx, bx, bh, out);
}